// round 4
// baseline (speedup 1.0000x reference)
#include <cuda_runtime.h>
#include <cuda_bf16.h>
#include <cstdint>

// ---------------------------------------------------------------------------
// B=512,N=200,C=512,NH=8,WS=5,HD=64.  M=102400 tokens.
// GEMM1: [M,512]x[512,1536]+b ; windowed attn ; GEMM2: [M,512]x[512,512]+b
// hi/lo bf16 split (3-term) on mma.sync m16n8k16; inputs pre-converted to
// fragment-image layout (validated in R3). R4: single-sync GEMM pipeline,
// deduped fragment loads, smem-staged coalesced image writes everywhere.
// ---------------------------------------------------------------------------
#define M_TOK   102400
#define K_DIM   512
#define N_QKV   1536
#define N_PROJ  512
#define WIN     5
#define HSCALE  0.125f
#define NKC     16        // K chunks of 32
#define CH_A    8192      // 128x32 bf16 A-image chunk bytes
#define CH_B    8192      // 32x128 bf16 B-image chunk bytes
#define STAGE_B 32768
#define NSTAGE  3

// ---------------- scratch (device globals; no allocation) ------------------
__device__ float          g_qkv[(size_t)M_TOK * N_QKV];
__device__ __nv_bfloat16  gA_hi[(size_t)M_TOK * K_DIM];
__device__ __nv_bfloat16  gA_lo[(size_t)M_TOK * K_DIM];
__device__ __nv_bfloat16  gO_hi[(size_t)M_TOK * K_DIM];
__device__ __nv_bfloat16  gO_lo[(size_t)M_TOK * K_DIM];
__device__ __nv_bfloat16  gB1_hi[(size_t)K_DIM * N_QKV];
__device__ __nv_bfloat16  gB1_lo[(size_t)K_DIM * N_QKV];
__device__ __nv_bfloat16  gB2_hi[(size_t)K_DIM * N_PROJ];
__device__ __nv_bfloat16  gB2_lo[(size_t)K_DIM * N_PROJ];

// ---------------------------- helpers ---------------------------------------
__device__ __forceinline__ uint32_t smem_u32(const void* p) {
    uint32_t a;
    asm("{ .reg .u64 t; cvta.to.shared.u64 t, %1; cvt.u32.u64 %0, t; }"
        : "=r"(a) : "l"(p));
    return a;
}
__device__ __forceinline__ void cp16(uint32_t d, const void* s) {
    asm volatile("cp.async.cg.shared.global [%0], [%1], 16;"
                 :: "r"(d), "l"(s) : "memory");
}
__device__ __forceinline__ void cp_commit() {
    asm volatile("cp.async.commit_group;" ::: "memory");
}
__device__ __forceinline__ void cp_wait1() {
    asm volatile("cp.async.wait_group 1;" ::: "memory");
}
__device__ __forceinline__ void mma_bf16(float4& d, uint4 a, uint2 b) {
    asm volatile(
        "mma.sync.aligned.m16n8k16.row.col.f32.bf16.bf16.f32 "
        "{%0,%1,%2,%3},{%4,%5,%6,%7},{%8,%9},{%0,%1,%2,%3};"
        : "+f"(d.x), "+f"(d.y), "+f"(d.z), "+f"(d.w)
        : "r"(a.x), "r"(a.y), "r"(a.z), "r"(a.w), "r"(b.x), "r"(b.y));
}
__device__ __forceinline__ unsigned short bf_bits(__nv_bfloat16 h) {
    return *reinterpret_cast<unsigned short*>(&h);
}
__device__ __forceinline__ void split1(float f, unsigned short& h,
                                       unsigned short& l) {
    __nv_bfloat16 bh = __float2bfloat16(f);
    __nv_bfloat16 bl = __float2bfloat16(f - __bfloat162float(bh));
    h = bf_bits(bh);
    l = bf_bits(bl);
}

// Fragment-image inner offsets (validated in R3):
// A (m-row row 0..127, kin 0..31):
//   (kf*8+mf)*512 + ((r&7)*4 + ((c&7)>>1))*16 + ((r>>3)+((c>>3)<<1))*4 + (c&1)*2
//   with kf=kin>>4, mf=row>>4, r=row&15, c=kin&15
// B (k-row kr 0..31, n 0..127):
//   ((kr>>4)*16 + (n>>3))*256 + ((n&7)*4 + ((kr&7)>>1))*8 + ((kr>>3)&1)*4 + (kr&1)*2
__device__ __forceinline__ int a_inner(int row, int kin) {
    int kf = kin >> 4, mf = row >> 4, r = row & 15, c = kin & 15;
    return (kf * 8 + mf) * 512 + ((r & 7) * 4 + ((c & 7) >> 1)) * 16 +
           ((r >> 3) + ((c >> 3) << 1)) * 4 + (c & 1) * 2;
}
__device__ __forceinline__ int b_inner(int kr, int n) {
    return ((kr >> 4) * 16 + (n >> 3)) * 256 +
           ((n & 7) * 4 + ((kr & 7) >> 1)) * 8 + ((kr >> 3) & 1) * 4 +
           (kr & 1) * 2;
}

// ---------------------------------------------------------------------------
// conv A: x [M,512] fp32 -> A images, smem-staged, coalesced 16B writes.
// block = (m-tile 128 rows, one k-chunk of 32). grid = 800*16.
// ---------------------------------------------------------------------------
__global__ void __launch_bounds__(256)
conv_A_staged(const float* __restrict__ x, char* __restrict__ hi,
              char* __restrict__ lo) {
    __shared__ char sh[CH_A];
    __shared__ char sl[CH_A];
    const int mt = blockIdx.x >> 4, kc = blockIdx.x & 15;
    const int t = threadIdx.x;
    const float* src = x + (size_t)mt * 128 * K_DIM + kc * 32;
#pragma unroll
    for (int i = 0; i < 4; ++i) {
        int f = t + i * 256;              // 1024 float4s total
        int row = f >> 3, c4 = (f & 7) * 4;
        float4 v = *(const float4*)(src + (size_t)row * K_DIM + c4);
        float vv[4] = {v.x, v.y, v.z, v.w};
#pragma unroll
        for (int jj = 0; jj < 4; ++jj) {
            unsigned short hs, ls;
            split1(vv[jj], hs, ls);
            int off = a_inner(row, c4 + jj);
            *(unsigned short*)(sh + off) = hs;
            *(unsigned short*)(sl + off) = ls;
        }
    }
    __syncthreads();
    size_t ob = ((size_t)mt * NKC + kc) * CH_A;
    const uint4* shv = (const uint4*)sh;
    const uint4* slv = (const uint4*)sl;
    uint4* gh = (uint4*)(hi + ob);
    uint4* gl = (uint4*)(lo + ob);
    gh[t * 2] = shv[t * 2];
    gh[t * 2 + 1] = shv[t * 2 + 1];
    gl[t * 2] = slv[t * 2];
    gl[t * 2 + 1] = slv[t * 2 + 1];
}

// ---------------------------------------------------------------------------
// conv W: W [K,N] fp32 -> B images, staged. block = (n-tile, k-chunk).
// ---------------------------------------------------------------------------
__global__ void __launch_bounds__(256)
conv_W_staged(const float* __restrict__ w, char* __restrict__ hi,
              char* __restrict__ lo, int N) {
    __shared__ char sh[CH_B];
    __shared__ char sl[CH_B];
    const int nt = blockIdx.x >> 4, kc = blockIdx.x & 15;
    const int t = threadIdx.x;
    const float* src = w + (size_t)(kc * 32) * N + nt * 128;
#pragma unroll
    for (int i = 0; i < 4; ++i) {
        int f = t + i * 256;              // 1024 float4s (32 rows x 32 f4)
        int kr = f >> 5, nc4 = (f & 31) * 4;
        float4 v = *(const float4*)(src + (size_t)kr * N + nc4);
        float vv[4] = {v.x, v.y, v.z, v.w};
#pragma unroll
        for (int jj = 0; jj < 4; ++jj) {
            unsigned short hs, ls;
            split1(vv[jj], hs, ls);
            int off = b_inner(kr, nc4 + jj);
            *(unsigned short*)(sh + off) = hs;
            *(unsigned short*)(sl + off) = ls;
        }
    }
    __syncthreads();
    size_t ob = ((size_t)nt * NKC + kc) * CH_B;
    const uint4* shv = (const uint4*)sh;
    const uint4* slv = (const uint4*)sl;
    uint4* gh = (uint4*)(hi + ob);
    uint4* gl = (uint4*)(lo + ob);
    gh[t * 2] = shv[t * 2];
    gh[t * 2 + 1] = shv[t * 2 + 1];
    gl[t * 2] = slv[t * 2];
    gl[t * 2 + 1] = slv[t * 2 + 1];
}

// ---------------------------------------------------------------------------
// HMMA split-bf16 GEMM. 128x128 CTA tile, 8 warps (4m x 2n), 3 cp.async
// stages, ONE __syncthreads per chunk, deduped fragment loads.
// ---------------------------------------------------------------------------
__global__ void __launch_bounds__(256, 2)
gemm_hmma_split(const char* __restrict__ gAh, const char* __restrict__ gAl,
                const char* __restrict__ gBh, const char* __restrict__ gBl,
                const float* __restrict__ bias, float* __restrict__ C,
                int N) {
    extern __shared__ __align__(128) char smem[];
    const int tid = threadIdx.x;
    const int lane = tid & 31, wid = tid >> 5;
    const int wm = wid & 3, wn = wid >> 2;
    const uint32_t dynB = smem_u32(smem);

    const size_t aBase = (size_t)blockIdx.y * NKC * CH_A;
    const size_t bBase = (size_t)blockIdx.x * NKC * CH_B;

    float4 acc[2][8];
#pragma unroll
    for (int mi = 0; mi < 2; ++mi)
#pragma unroll
        for (int ni = 0; ni < 8; ++ni)
            acc[mi][ni] = make_float4(0.f, 0.f, 0.f, 0.f);

    auto issue = [&](int kc, int s) {
        const char* srcs[4] = {gAh + aBase + (size_t)kc * CH_A,
                               gAl + aBase + (size_t)kc * CH_A,
                               gBh + bBase + (size_t)kc * CH_B,
                               gBl + bBase + (size_t)kc * CH_B};
        uint32_t dst = dynB + s * STAGE_B;
#pragma unroll
        for (int b = 0; b < 4; ++b) {
#pragma unroll
            for (int i = 0; i < 2; ++i) {
                int off = (tid + i * 256) * 16;
                cp16(dst + b * 8192 + off, srcs[b] + off);
            }
        }
    };

    issue(0, 0);
    cp_commit();
    issue(1, 1);
    cp_commit();

    for (int kc = 0; kc < NKC; ++kc) {
        const int s = kc % NSTAGE;
        cp_wait1();
        __syncthreads();
        if (kc + 2 < NKC) issue(kc + 2, (kc + 2) % NSTAGE);
        cp_commit();

        const char* st = smem + s * STAGE_B;
#pragma unroll
        for (int kf = 0; kf < 2; ++kf) {
            const char* af = st + (kf * 8 + wm * 2) * 512 + lane * 16;
            const char* bf = st + 16384 + (kf * 16 + wn * 8) * 256 + lane * 8;
            uint4 ah0 = *(const uint4*)af;
            uint4 ah1 = *(const uint4*)(af + 512);
            uint2 bh[8];
#pragma unroll
            for (int ni = 0; ni < 8; ++ni)
                bh[ni] = *(const uint2*)(bf + ni * 256);
#pragma unroll
            for (int ni = 0; ni < 8; ++ni) {
                mma_bf16(acc[0][ni], ah0, bh[ni]);
                mma_bf16(acc[1][ni], ah1, bh[ni]);
            }
            uint4 al0 = *(const uint4*)(af + 8192);
            uint4 al1 = *(const uint4*)(af + 8192 + 512);
#pragma unroll
            for (int ni = 0; ni < 8; ++ni) {
                mma_bf16(acc[0][ni], al0, bh[ni]);
                mma_bf16(acc[1][ni], al1, bh[ni]);
            }
#pragma unroll
            for (int ni = 0; ni < 8; ++ni) {
                uint2 bl = *(const uint2*)(bf + 8192 + ni * 256);
                mma_bf16(acc[0][ni], ah0, bl);
                mma_bf16(acc[1][ni], ah1, bl);
            }
        }
    }

    const int row0 = blockIdx.y * 128 + wm * 32 + (lane >> 2);
    const int col0 = blockIdx.x * 128 + wn * 64 + (lane & 3) * 2;
#pragma unroll
    for (int ni = 0; ni < 8; ++ni) {
        int c = col0 + ni * 8;
        float bx = bias[c], by = bias[c + 1];
#pragma unroll
        for (int mi = 0; mi < 2; ++mi) {
            float4 v = acc[mi][ni];
            float* p0 = C + (size_t)(row0 + mi * 16) * N + c;
            float* p1 = C + (size_t)(row0 + mi * 16 + 8) * N + c;
            *(float2*)p0 = make_float2(v.x + bx, v.y + by);
            *(float2*)p1 = make_float2(v.z + bx, v.w + by);
        }
    }
}

// ---------------------------------------------------------------------------
// Windowed attention: block = 16 windows (80 tokens), warp = head.
// Phase 1: compute o, stage packed (hi|lo<<16) in smem.
// Phase 2: write full 512B fragments coalesced (uint4 per lane).
// ---------------------------------------------------------------------------
__global__ void __launch_bounds__(256)
win_attn_staged(const float* __restrict__ qkv, char* __restrict__ oh,
                char* __restrict__ ol) {
    extern __shared__ uint32_t stage[];   // [8 heads][80 rows][64 dims]
    const int h = threadIdx.x >> 5;
    const int lane = threadIdx.x & 31;
    const int m0b = blockIdx.x * 80;

    for (int w = 0; w < 16; ++w) {
        const int m0 = m0b + w * 5;
        const float* base = qkv + (size_t)m0 * N_QKV + h * 64;

        float q[WIN][2], k[WIN][2], v[WIN][2];
#pragma unroll
        for (int i = 0; i < WIN; ++i) {
            const float* r = base + (size_t)i * N_QKV;
            q[i][0] = r[lane];        q[i][1] = r[lane + 32];
            k[i][0] = r[512 + lane];  k[i][1] = r[512 + lane + 32];
            v[i][0] = r[1024 + lane]; v[i][1] = r[1024 + lane + 32];
        }

        float s[WIN][WIN];
#pragma unroll
        for (int i = 0; i < WIN; ++i)
#pragma unroll
            for (int j = 0; j < WIN; ++j) {
                float p = q[i][0] * k[j][0] + q[i][1] * k[j][1];
                p += __shfl_xor_sync(0xffffffffu, p, 16);
                p += __shfl_xor_sync(0xffffffffu, p, 8);
                p += __shfl_xor_sync(0xffffffffu, p, 4);
                p += __shfl_xor_sync(0xffffffffu, p, 2);
                p += __shfl_xor_sync(0xffffffffu, p, 1);
                s[i][j] = p * HSCALE;
            }

#pragma unroll
        for (int i = 0; i < WIN; ++i) {
            float mx = s[i][0];
#pragma unroll
            for (int j = 1; j < WIN; ++j) mx = fmaxf(mx, s[i][j]);
            float sum = 0.0f;
#pragma unroll
            for (int j = 0; j < WIN; ++j) {
                s[i][j] = __expf(s[i][j] - mx);
                sum += s[i][j];
            }
            float inv = 1.0f / sum;
            float o0 = 0.0f, o1 = 0.0f;
#pragma unroll
            for (int j = 0; j < WIN; ++j) {
                float a = s[i][j] * inv;
                o0 += a * v[j][0];
                o1 += a * v[j][1];
            }
            unsigned short hs, ls;
            int row = w * 5 + i;
            split1(o0, hs, ls);
            stage[(h * 80 + row) * 64 + lane] = (uint32_t)hs | ((uint32_t)ls << 16);
            split1(o1, hs, ls);
            stage[(h * 80 + row) * 64 + lane + 32] =
                (uint32_t)hs | ((uint32_t)ls << 16);
        }
    }
    __syncthreads();

    // phase 2: warp h writes its 20 (hi,lo) fragment pairs coalesced
#pragma unroll
    for (int mf = 0; mf < 5; ++mf) {
        const int mG0 = m0b + mf * 16;            // frag base (multiple of 16)
        const int tile = mG0 >> 7;
        const int mfp = (mG0 & 127) >> 4;
#pragma unroll
        for (int kcl = 0; kcl < 2; ++kcl) {
#pragma unroll
            for (int kf = 0; kf < 2; ++kf) {
                const uint32_t* sp =
                    stage + (h * 80 + mf * 16) * 64 + kcl * 32 + kf * 16;
                uint32_t hih[4], loh[4];
#pragma unroll
                for (int j = 0; j < 4; ++j) {
                    // hw = 2j, 2j+1
                    int r0 = (lane >> 2) + 8 * (j & 1);
                    int cbase = (lane & 3) * 2 + 8 * (j >> 1);
                    uint32_t v0 = sp[r0 * 64 + cbase];
                    uint32_t v1 = sp[r0 * 64 + cbase + 1];
                    hih[j] = (v0 & 0xffffu) | ((v1 & 0xffffu) << 16);
                    loh[j] = (v0 >> 16) | ((v1 >> 16) << 16);
                }
                size_t off = ((size_t)tile * NKC + 2 * h + kcl) * CH_A +
                             (size_t)(kf * 8 + mfp) * 512 + (size_t)lane * 16;
                *(uint4*)(oh + off) = make_uint4(hih[0], hih[1], hih[2], hih[3]);
                *(uint4*)(ol + off) = make_uint4(loh[0], loh[1], loh[2], loh[3]);
            }
        }
    }
}

// ---------------------------------------------------------------------------
// kernel_launch
// ---------------------------------------------------------------------------
extern "C" void kernel_launch(void* const* d_in, const int* in_sizes, int n_in,
                              void* d_out, int out_size) {
    const float* x      = (const float*)d_in[0];
    const float* qkv_w  = (const float*)d_in[1];
    const float* qkv_b  = (const float*)d_in[2];
    const float* proj_w = (const float*)d_in[3];
    const float* proj_b = (const float*)d_in[4];
    float* out = (float*)d_out;

    float* qkvp;
    char *Ah, *Al, *Oh, *Ol, *B1h, *B1l, *B2h, *B2l;
    cudaGetSymbolAddress((void**)&qkvp, g_qkv);
    cudaGetSymbolAddress((void**)&Ah, gA_hi);
    cudaGetSymbolAddress((void**)&Al, gA_lo);
    cudaGetSymbolAddress((void**)&Oh, gO_hi);
    cudaGetSymbolAddress((void**)&Ol, gO_lo);
    cudaGetSymbolAddress((void**)&B1h, gB1_hi);
    cudaGetSymbolAddress((void**)&B1l, gB1_lo);
    cudaGetSymbolAddress((void**)&B2h, gB2_hi);
    cudaGetSymbolAddress((void**)&B2l, gB2_lo);

    static bool attr_set = false;
    if (!attr_set) {
        cudaFuncSetAttribute(gemm_hmma_split,
                             cudaFuncAttributeMaxDynamicSharedMemorySize,
                             NSTAGE * STAGE_B);
        cudaFuncSetAttribute(win_attn_staged,
                             cudaFuncAttributeMaxDynamicSharedMemorySize,
                             8 * 80 * 64 * 4);
        attr_set = true;
    }

    conv_A_staged<<<(M_TOK / 128) * NKC, 256>>>(x, Ah, Al);
    conv_W_staged<<<(N_QKV / 128) * NKC, 256>>>(qkv_w, B1h, B1l, N_QKV);
    conv_W_staged<<<(N_PROJ / 128) * NKC, 256>>>(proj_w, B2h, B2l, N_PROJ);

    {   // GEMM1 -> g_qkv (fp32 row-major for attention)
        dim3 grid(N_QKV / 128, M_TOK / 128);
        gemm_hmma_split<<<grid, 256, NSTAGE * STAGE_B>>>(Ah, Al, B1h, B1l,
                                                         qkv_b, qkvp, N_QKV);
    }

    win_attn_staged<<<M_TOK / 80, 256, 8 * 80 * 64 * 4>>>(qkvp, Oh, Ol);

    {   // GEMM2 -> out
        dim3 grid(N_PROJ / 128, M_TOK / 128);
        gemm_hmma_split<<<grid, 256, NSTAGE * STAGE_B>>>(Oh, Ol, B2h, B2l,
                                                         proj_b, out, N_PROJ);
    }
}

// round 5
// speedup vs baseline: 1.1326x; 1.1326x over previous
#include <cuda_runtime.h>
#include <cuda_bf16.h>
#include <cstdint>

// ---------------------------------------------------------------------------
// B=512,N=200,C=512,NH=8,WS=5,HD=64.  M=102400 tokens.
// hi/lo bf16 split (3-term) on mma.sync m16n8k16 HMMA.
// R5: B-images interleave hi/lo per fragment (1 LDS.128 per B frag pair),
// R3-style lightweight attention, R4 single-sync GEMM pipeline.
// ---------------------------------------------------------------------------
#define M_TOK   102400
#define K_DIM   512
#define N_QKV   1536
#define N_PROJ  512
#define WIN     5
#define HSCALE  0.125f
#define NKC     16        // K chunks of 32
#define CH_A    8192      // 128x32 bf16 A-image chunk bytes (hi or lo)
#define CH_BI   16384     // 32x128 interleaved (hi|lo) B-image chunk bytes
#define STAGE_B 32768     // Ah(8K)+Al(8K)+Bi(16K)
#define NSTAGE  3

// ---------------- scratch (device globals; no allocation) ------------------
__device__ float          g_qkv[(size_t)M_TOK * N_QKV];
__device__ __nv_bfloat16  gA_hi[(size_t)M_TOK * K_DIM];
__device__ __nv_bfloat16  gA_lo[(size_t)M_TOK * K_DIM];
__device__ __nv_bfloat16  gO_hi[(size_t)M_TOK * K_DIM];
__device__ __nv_bfloat16  gO_lo[(size_t)M_TOK * K_DIM];
__device__ __nv_bfloat16  gB1_i[(size_t)2 * K_DIM * N_QKV];
__device__ __nv_bfloat16  gB2_i[(size_t)2 * K_DIM * N_PROJ];

// ---------------------------- helpers ---------------------------------------
__device__ __forceinline__ uint32_t smem_u32(const void* p) {
    uint32_t a;
    asm("{ .reg .u64 t; cvta.to.shared.u64 t, %1; cvt.u32.u64 %0, t; }"
        : "=r"(a) : "l"(p));
    return a;
}
__device__ __forceinline__ void cp16(uint32_t d, const void* s) {
    asm volatile("cp.async.cg.shared.global [%0], [%1], 16;"
                 :: "r"(d), "l"(s) : "memory");
}
__device__ __forceinline__ void cp_commit() {
    asm volatile("cp.async.commit_group;" ::: "memory");
}
__device__ __forceinline__ void cp_wait1() {
    asm volatile("cp.async.wait_group 1;" ::: "memory");
}
__device__ __forceinline__ void mma_bf16(float4& d, uint4 a, uint32_t b0,
                                         uint32_t b1) {
    asm volatile(
        "mma.sync.aligned.m16n8k16.row.col.f32.bf16.bf16.f32 "
        "{%0,%1,%2,%3},{%4,%5,%6,%7},{%8,%9},{%0,%1,%2,%3};"
        : "+f"(d.x), "+f"(d.y), "+f"(d.z), "+f"(d.w)
        : "r"(a.x), "r"(a.y), "r"(a.z), "r"(a.w), "r"(b0), "r"(b1));
}
__device__ __forceinline__ unsigned short bf_bits(__nv_bfloat16 h) {
    return *reinterpret_cast<unsigned short*>(&h);
}
__device__ __forceinline__ void split1(float f, unsigned short& h,
                                       unsigned short& l) {
    __nv_bfloat16 bh = __float2bfloat16(f);
    __nv_bfloat16 bl = __float2bfloat16(f - __bfloat162float(bh));
    h = bf_bits(bh);
    l = bf_bits(bl);
}

// A-image inner offset (validated R3/R4):
__device__ __forceinline__ int a_inner(int row, int kin) {
    int kf = kin >> 4, mf = row >> 4, r = row & 15, c = kin & 15;
    return (kf * 8 + mf) * 512 + ((r & 7) * 4 + ((c & 7) >> 1)) * 16 +
           ((r >> 3) + ((c >> 3) << 1)) * 4 + (c & 1) * 2;
}
// Interleaved B-image inner offset: fragment (kf,nf) occupies 512B;
// thread t=(n%8)*4+((k%8)/2) holds 16B: [hi j0, hi j1, lo j0, lo j1]
__device__ __forceinline__ int bi_inner(int kr, int n, int hilo) {
    int kf = kr >> 4, nf = n >> 3;
    int t = (n & 7) * 4 + ((kr & 7) >> 1);
    return (kf * 16 + nf) * 512 + t * 16 + hilo * 8 + ((kr >> 3) & 1) * 4 +
           (kr & 1) * 2;
}

// ---------------------------------------------------------------------------
// conv A: x [M,512] fp32 -> A images (hi/lo, separate), smem-staged.
// block = (m-tile 128, k-chunk 32). grid = 800*16.
// ---------------------------------------------------------------------------
__global__ void __launch_bounds__(256)
conv_A_staged(const float* __restrict__ x, char* __restrict__ hi,
              char* __restrict__ lo) {
    __shared__ char sh[CH_A];
    __shared__ char sl[CH_A];
    const int mt = blockIdx.x >> 4, kc = blockIdx.x & 15;
    const int t = threadIdx.x;
    const float* src = x + (size_t)mt * 128 * K_DIM + kc * 32;
#pragma unroll
    for (int i = 0; i < 4; ++i) {
        int f = t + i * 256;
        int row = f >> 3, c4 = (f & 7) * 4;
        float4 v = *(const float4*)(src + (size_t)row * K_DIM + c4);
        float vv[4] = {v.x, v.y, v.z, v.w};
#pragma unroll
        for (int jj = 0; jj < 4; ++jj) {
            unsigned short hs, ls;
            split1(vv[jj], hs, ls);
            int off = a_inner(row, c4 + jj);
            *(unsigned short*)(sh + off) = hs;
            *(unsigned short*)(sl + off) = ls;
        }
    }
    __syncthreads();
    size_t ob = ((size_t)mt * NKC + kc) * CH_A;
    const uint4* shv = (const uint4*)sh;
    const uint4* slv = (const uint4*)sl;
    uint4* gh = (uint4*)(hi + ob);
    uint4* gl = (uint4*)(lo + ob);
    gh[t * 2] = shv[t * 2];
    gh[t * 2 + 1] = shv[t * 2 + 1];
    gl[t * 2] = slv[t * 2];
    gl[t * 2 + 1] = slv[t * 2 + 1];
}

// ---------------------------------------------------------------------------
// conv W: W [K,N] fp32 -> interleaved B images, staged.
// block = (n-tile, k-chunk); chunk = 32k x 128n -> 16KB image.
// ---------------------------------------------------------------------------
__global__ void __launch_bounds__(256)
conv_W_staged(const float* __restrict__ w, char* __restrict__ bi, int N) {
    __shared__ char sb[CH_BI];
    const int nt = blockIdx.x >> 4, kc = blockIdx.x & 15;
    const int t = threadIdx.x;
    const float* src = w + (size_t)(kc * 32) * N + nt * 128;
#pragma unroll
    for (int i = 0; i < 4; ++i) {
        int f = t + i * 256;              // 1024 float4 (32 rows x 32 f4)
        int kr = f >> 5, nc4 = (f & 31) * 4;
        float4 v = *(const float4*)(src + (size_t)kr * N + nc4);
        float vv[4] = {v.x, v.y, v.z, v.w};
#pragma unroll
        for (int jj = 0; jj < 4; ++jj) {
            unsigned short hs, ls;
            split1(vv[jj], hs, ls);
            *(unsigned short*)(sb + bi_inner(kr, nc4 + jj, 0)) = hs;
            *(unsigned short*)(sb + bi_inner(kr, nc4 + jj, 1)) = ls;
        }
    }
    __syncthreads();
    size_t ob = ((size_t)nt * NKC + kc) * CH_BI;
    const uint4* sv = (const uint4*)sb;
    uint4* gv = (uint4*)(bi + ob);
#pragma unroll
    for (int i = 0; i < 4; ++i) gv[t + i * 256] = sv[t + i * 256];
}

// ---------------------------------------------------------------------------
// HMMA split-bf16 GEMM. 128x128 CTA tile, 8 warps (4m x 2n), 3 cp.async
// stages, one sync/chunk, interleaved-B LDS.128 loads.
// ---------------------------------------------------------------------------
__global__ void __launch_bounds__(256, 2)
gemm_hmma_split(const char* __restrict__ gAh, const char* __restrict__ gAl,
                const char* __restrict__ gBi, const float* __restrict__ bias,
                float* __restrict__ C, int N) {
    extern __shared__ __align__(128) char smem[];
    const int tid = threadIdx.x;
    const int lane = tid & 31, wid = tid >> 5;
    const int wm = wid & 3, wn = wid >> 2;
    const uint32_t dynB = smem_u32(smem);

    const size_t aBase = (size_t)blockIdx.y * NKC * CH_A;
    const size_t bBase = (size_t)blockIdx.x * NKC * CH_BI;

    float4 acc[2][8];
#pragma unroll
    for (int mi = 0; mi < 2; ++mi)
#pragma unroll
        for (int ni = 0; ni < 8; ++ni)
            acc[mi][ni] = make_float4(0.f, 0.f, 0.f, 0.f);

    auto issue = [&](int kc, int s) {
        uint32_t dst = dynB + s * STAGE_B;
        const char* ah = gAh + aBase + (size_t)kc * CH_A;
        const char* al = gAl + aBase + (size_t)kc * CH_A;
        const char* bi = gBi + bBase + (size_t)kc * CH_BI;
        {
            int off = tid * 16;           // 4KB sweep over 8KB buffers
            cp16(dst + off, ah + off);
            cp16(dst + 4096 + off, ah + 4096 + off);
            cp16(dst + 8192 + off, al + off);
            cp16(dst + 12288 + off, al + 4096 + off);
#pragma unroll
            for (int i = 0; i < 4; ++i)
                cp16(dst + 16384 + off + i * 4096, bi + off + i * 4096);
        }
    };

    issue(0, 0);
    cp_commit();
    issue(1, 1);
    cp_commit();

    for (int kc = 0; kc < NKC; ++kc) {
        const int s = kc % NSTAGE;
        cp_wait1();
        __syncthreads();
        if (kc + 2 < NKC) issue(kc + 2, (kc + 2) % NSTAGE);
        cp_commit();

        const char* st = smem + s * STAGE_B;
#pragma unroll
        for (int kf = 0; kf < 2; ++kf) {
            const char* af = st + (kf * 8 + wm * 2) * 512 + lane * 16;
            uint4 ah0 = *(const uint4*)af;
            uint4 ah1 = *(const uint4*)(af + 512);
            uint4 al0 = *(const uint4*)(af + 8192);
            uint4 al1 = *(const uint4*)(af + 8192 + 512);
            const char* bf =
                st + 16384 + (kf * 16 + wn * 8) * 512 + lane * 16;
#pragma unroll
            for (int half = 0; half < 2; ++half) {
                uint4 b[4];
#pragma unroll
                for (int j = 0; j < 4; ++j)
                    b[j] = *(const uint4*)(bf + (half * 4 + j) * 512);
#pragma unroll
                for (int j = 0; j < 4; ++j) {
                    int ni = half * 4 + j;
                    mma_bf16(acc[0][ni], ah0, b[j].x, b[j].y);
                    mma_bf16(acc[1][ni], ah1, b[j].x, b[j].y);
                    mma_bf16(acc[0][ni], al0, b[j].x, b[j].y);
                    mma_bf16(acc[1][ni], al1, b[j].x, b[j].y);
                    mma_bf16(acc[0][ni], ah0, b[j].z, b[j].w);
                    mma_bf16(acc[1][ni], ah1, b[j].z, b[j].w);
                }
            }
        }
    }

    const int row0 = blockIdx.y * 128 + wm * 32 + (lane >> 2);
    const int col0 = blockIdx.x * 128 + wn * 64 + (lane & 3) * 2;
#pragma unroll
    for (int ni = 0; ni < 8; ++ni) {
        int c = col0 + ni * 8;
        float bx = bias[c], by = bias[c + 1];
#pragma unroll
        for (int mi = 0; mi < 2; ++mi) {
            float4 v = acc[mi][ni];
            float* p0 = C + (size_t)(row0 + mi * 16) * N + c;
            float* p1 = C + (size_t)(row0 + mi * 16 + 8) * N + c;
            *(float2*)p0 = make_float2(v.x + bx, v.y + by);
            *(float2*)p1 = make_float2(v.z + bx, v.w + by);
        }
    }
}

// ---------------------------------------------------------------------------
// Windowed attention (R3 version — lightweight, one block per window).
// Emits output directly as hi/lo A-fragment images for GEMM2.
// ---------------------------------------------------------------------------
__global__ void __launch_bounds__(256)
win_attn_kernel(const float* __restrict__ qkv, char* __restrict__ oh,
                char* __restrict__ ol) {
    const int win = blockIdx.x;
    const int h = threadIdx.x >> 5;
    const int lane = threadIdx.x & 31;
    const int m0 = win * WIN;

    const float* base = qkv + (size_t)m0 * N_QKV + h * 64;

    float q[WIN][2], k[WIN][2], v[WIN][2];
#pragma unroll
    for (int i = 0; i < WIN; ++i) {
        const float* r = base + (size_t)i * N_QKV;
        q[i][0] = r[lane];        q[i][1] = r[lane + 32];
        k[i][0] = r[512 + lane];  k[i][1] = r[512 + lane + 32];
        v[i][0] = r[1024 + lane]; v[i][1] = r[1024 + lane + 32];
    }

    float s[WIN][WIN];
#pragma unroll
    for (int i = 0; i < WIN; ++i)
#pragma unroll
        for (int j = 0; j < WIN; ++j) {
            float p = q[i][0] * k[j][0] + q[i][1] * k[j][1];
            p += __shfl_xor_sync(0xffffffffu, p, 16);
            p += __shfl_xor_sync(0xffffffffu, p, 8);
            p += __shfl_xor_sync(0xffffffffu, p, 4);
            p += __shfl_xor_sync(0xffffffffu, p, 2);
            p += __shfl_xor_sync(0xffffffffu, p, 1);
            s[i][j] = p * HSCALE;
        }

    const int kf = lane >> 4, c = lane & 15;
    const int inner = ((c & 7) >> 1) * 16 + ((c >> 3) << 1) * 4 + (c & 1) * 2;

#pragma unroll
    for (int i = 0; i < WIN; ++i) {
        float mx = s[i][0];
#pragma unroll
        for (int j = 1; j < WIN; ++j) mx = fmaxf(mx, s[i][j]);
        float sum = 0.0f;
#pragma unroll
        for (int j = 0; j < WIN; ++j) {
            s[i][j] = __expf(s[i][j] - mx);
            sum += s[i][j];
        }
        float inv = 1.0f / sum;
        float o0 = 0.0f, o1 = 0.0f;
#pragma unroll
        for (int j = 0; j < WIN; ++j) {
            float a = s[i][j] * inv;
            o0 += a * v[j][0];
            o1 += a * v[j][1];
        }
        int m = m0 + i;
        int r = m & 15, mf = (m & 127) >> 4;
        size_t tb = ((size_t)(m >> 7) * NKC + 2 * h) * CH_A +
                    (size_t)(kf * 8 + mf) * 512 +
                    (size_t)((r & 7) * 4) * 16 + (size_t)(r >> 3) * 4 + inner;
        unsigned short hs, ls;
        split1(o0, hs, ls);
        *(unsigned short*)(oh + tb) = hs;
        *(unsigned short*)(ol + tb) = ls;
        split1(o1, hs, ls);
        *(unsigned short*)(oh + tb + CH_A) = hs;
        *(unsigned short*)(ol + tb + CH_A) = ls;
    }
}

// ---------------------------------------------------------------------------
// kernel_launch
// ---------------------------------------------------------------------------
extern "C" void kernel_launch(void* const* d_in, const int* in_sizes, int n_in,
                              void* d_out, int out_size) {
    const float* x      = (const float*)d_in[0];
    const float* qkv_w  = (const float*)d_in[1];
    const float* qkv_b  = (const float*)d_in[2];
    const float* proj_w = (const float*)d_in[3];
    const float* proj_b = (const float*)d_in[4];
    float* out = (float*)d_out;

    float* qkvp;
    char *Ah, *Al, *Oh, *Ol, *B1, *B2;
    cudaGetSymbolAddress((void**)&qkvp, g_qkv);
    cudaGetSymbolAddress((void**)&Ah, gA_hi);
    cudaGetSymbolAddress((void**)&Al, gA_lo);
    cudaGetSymbolAddress((void**)&Oh, gO_hi);
    cudaGetSymbolAddress((void**)&Ol, gO_lo);
    cudaGetSymbolAddress((void**)&B1, gB1_i);
    cudaGetSymbolAddress((void**)&B2, gB2_i);

    static bool attr_set = false;
    if (!attr_set) {
        cudaFuncSetAttribute(gemm_hmma_split,
                             cudaFuncAttributeMaxDynamicSharedMemorySize,
                             NSTAGE * STAGE_B);
        attr_set = true;
    }

    conv_A_staged<<<(M_TOK / 128) * NKC, 256>>>(x, Ah, Al);
    conv_W_staged<<<(N_QKV / 128) * NKC, 256>>>(qkv_w, B1, N_QKV);
    conv_W_staged<<<(N_PROJ / 128) * NKC, 256>>>(proj_w, B2, N_PROJ);

    {   // GEMM1 -> g_qkv
        dim3 grid(N_QKV / 128, M_TOK / 128);
        gemm_hmma_split<<<grid, 256, NSTAGE * STAGE_B>>>(Ah, Al, B1,
                                                         qkv_b, qkvp, N_QKV);
    }

    win_attn_kernel<<<M_TOK / WIN, 256>>>(qkvp, Oh, Ol);

    {   // GEMM2 -> out
        dim3 grid(N_PROJ / 128, M_TOK / 128);
        gemm_hmma_split<<<grid, 256, NSTAGE * STAGE_B>>>(Oh, Ol, B2,
                                                         proj_b, out, N_PROJ);
    }
}

// round 6
// speedup vs baseline: 1.5423x; 1.3618x over previous
#include <cuda_runtime.h>
#include <cuda_fp16.h>
#include <cstdint>

// ---------------------------------------------------------------------------
// B=512,N=200,C=512,NH=8,WS=5,HD=64.  M=102400 tokens.
// R6: fp16 one-sided split: A = Ah+Al (fp16 pair), B = single fp16.
// 2 MMA terms (was 3 bf16 terms). mma.sync m16n8k16.f32.f16.f16.f32.
// ---------------------------------------------------------------------------
#define M_TOK   102400
#define K_DIM   512
#define N_QKV   1536
#define N_PROJ  512
#define WIN     5
#define HSCALE  0.125f
#define NKC     16        // K chunks of 32
#define CH_A    8192      // 128x32 fp16 A-image chunk bytes (hi or lo)
#define CH_B    8192      // 32x128 fp16 B-image chunk bytes (paired frags)
#define STAGE_B 24576     // Ah(8K)+Al(8K)+B(8K)
#define NSTAGE  3

// ---------------- scratch (device globals; no allocation) ------------------
__device__ float   g_qkv[(size_t)M_TOK * N_QKV];
__device__ __half  gA_hi[(size_t)M_TOK * K_DIM];
__device__ __half  gA_lo[(size_t)M_TOK * K_DIM];
__device__ __half  gO_hi[(size_t)M_TOK * K_DIM];
__device__ __half  gO_lo[(size_t)M_TOK * K_DIM];
__device__ __half  gB1_i[(size_t)K_DIM * N_QKV];
__device__ __half  gB2_i[(size_t)K_DIM * N_PROJ];

// ---------------------------- helpers ---------------------------------------
__device__ __forceinline__ uint32_t smem_u32(const void* p) {
    uint32_t a;
    asm("{ .reg .u64 t; cvta.to.shared.u64 t, %1; cvt.u32.u64 %0, t; }"
        : "=r"(a) : "l"(p));
    return a;
}
__device__ __forceinline__ void cp16(uint32_t d, const void* s) {
    asm volatile("cp.async.cg.shared.global [%0], [%1], 16;"
                 :: "r"(d), "l"(s) : "memory");
}
__device__ __forceinline__ void cp_commit() {
    asm volatile("cp.async.commit_group;" ::: "memory");
}
__device__ __forceinline__ void cp_wait1() {
    asm volatile("cp.async.wait_group 1;" ::: "memory");
}
__device__ __forceinline__ void mma_f16(float4& d, uint4 a, uint32_t b0,
                                        uint32_t b1) {
    asm volatile(
        "mma.sync.aligned.m16n8k16.row.col.f32.f16.f16.f32 "
        "{%0,%1,%2,%3},{%4,%5,%6,%7},{%8,%9},{%0,%1,%2,%3};"
        : "+f"(d.x), "+f"(d.y), "+f"(d.z), "+f"(d.w)
        : "r"(a.x), "r"(a.y), "r"(a.z), "r"(a.w), "r"(b0), "r"(b1));
}
__device__ __forceinline__ unsigned short h_bits(__half h) {
    return *reinterpret_cast<unsigned short*>(&h);
}
__device__ __forceinline__ void split1(float f, unsigned short& h,
                                       unsigned short& l) {
    __half hh = __float2half(f);
    __half hl = __float2half(f - __half2float(hh));
    h = h_bits(hh);
    l = h_bits(hl);
}
__device__ __forceinline__ unsigned short h_single(float f) {
    __half hh = __float2half(f);
    return h_bits(hh);
}

// A-image inner offset (validated R3-R5; element layout identical, fp16 now):
__device__ __forceinline__ int a_inner(int row, int kin) {
    int kf = kin >> 4, mf = row >> 4, r = row & 15, c = kin & 15;
    return (kf * 8 + mf) * 512 + ((r & 7) * 4 + ((c & 7) >> 1)) * 16 +
           ((r >> 3) + ((c >> 3) << 1)) * 4 + (c & 1) * 2;
}
// Paired B-image: fragment pair (nf even|odd) in one 512B block; thread slot
// holds 16B = [even frag 8B | odd frag 8B]. Same per-fragment element map as
// the validated b_inner, regrouped for LDS.128.
__device__ __forceinline__ int bp_inner(int kr, int n) {
    int kf = kr >> 4, nfp = n >> 4, odd = (n >> 3) & 1;
    int t = (n & 7) * 4 + ((kr & 7) >> 1);
    return (kf * 8 + nfp) * 512 + t * 16 + odd * 8 + ((kr >> 3) & 1) * 4 +
           (kr & 1) * 2;
}

// ---------------------------------------------------------------------------
// conv A: x [M,512] fp32 -> A images (hi/lo fp16), smem-staged.
// block = (m-tile 128, k-chunk 32). grid = 800*16.
// ---------------------------------------------------------------------------
__global__ void __launch_bounds__(256)
conv_A_staged(const float* __restrict__ x, char* __restrict__ hi,
              char* __restrict__ lo) {
    __shared__ char sh[CH_A];
    __shared__ char sl[CH_A];
    const int mt = blockIdx.x >> 4, kc = blockIdx.x & 15;
    const int t = threadIdx.x;
    const float* src = x + (size_t)mt * 128 * K_DIM + kc * 32;
#pragma unroll
    for (int i = 0; i < 4; ++i) {
        int f = t + i * 256;
        int row = f >> 3, c4 = (f & 7) * 4;
        float4 v = *(const float4*)(src + (size_t)row * K_DIM + c4);
        float vv[4] = {v.x, v.y, v.z, v.w};
#pragma unroll
        for (int jj = 0; jj < 4; ++jj) {
            unsigned short hs, ls;
            split1(vv[jj], hs, ls);
            int off = a_inner(row, c4 + jj);
            *(unsigned short*)(sh + off) = hs;
            *(unsigned short*)(sl + off) = ls;
        }
    }
    __syncthreads();
    size_t ob = ((size_t)mt * NKC + kc) * CH_A;
    const uint4* shv = (const uint4*)sh;
    const uint4* slv = (const uint4*)sl;
    uint4* gh = (uint4*)(hi + ob);
    uint4* gl = (uint4*)(lo + ob);
    gh[t * 2] = shv[t * 2];
    gh[t * 2 + 1] = shv[t * 2 + 1];
    gl[t * 2] = slv[t * 2];
    gl[t * 2 + 1] = slv[t * 2 + 1];
}

// ---------------------------------------------------------------------------
// conv W: W [K,N] fp32 -> single fp16 paired B images, staged.
// block = (n-tile, k-chunk); chunk = 32k x 128n -> 8KB image.
// ---------------------------------------------------------------------------
__global__ void __launch_bounds__(256)
conv_W_staged(const float* __restrict__ w, char* __restrict__ bi, int N) {
    __shared__ char sb[CH_B];
    const int nt = blockIdx.x >> 4, kc = blockIdx.x & 15;
    const int t = threadIdx.x;
    const float* src = w + (size_t)(kc * 32) * N + nt * 128;
#pragma unroll
    for (int i = 0; i < 4; ++i) {
        int f = t + i * 256;              // 1024 float4 (32 rows x 32 f4)
        int kr = f >> 5, nc4 = (f & 31) * 4;
        float4 v = *(const float4*)(src + (size_t)kr * N + nc4);
        float vv[4] = {v.x, v.y, v.z, v.w};
#pragma unroll
        for (int jj = 0; jj < 4; ++jj)
            *(unsigned short*)(sb + bp_inner(kr, nc4 + jj)) =
                h_single(vv[jj]);
    }
    __syncthreads();
    size_t ob = ((size_t)nt * NKC + kc) * CH_B;
    const uint4* sv = (const uint4*)sb;
    uint4* gv = (uint4*)(bi + ob);
    gv[t * 2] = sv[t * 2];
    gv[t * 2 + 1] = sv[t * 2 + 1];
}

// ---------------------------------------------------------------------------
// HMMA fp16 2-term GEMM. 128x128 CTA tile, 8 warps (4m x 2n), 3 cp.async
// stages, one sync/chunk.
// ---------------------------------------------------------------------------
__global__ void __launch_bounds__(256, 2)
gemm_hmma_split(const char* __restrict__ gAh, const char* __restrict__ gAl,
                const char* __restrict__ gBi, const float* __restrict__ bias,
                float* __restrict__ C, int N) {
    extern __shared__ __align__(128) char smem[];
    const int tid = threadIdx.x;
    const int lane = tid & 31, wid = tid >> 5;
    const int wm = wid & 3, wn = wid >> 2;
    const uint32_t dynB = smem_u32(smem);

    const size_t aBase = (size_t)blockIdx.y * NKC * CH_A;
    const size_t bBase = (size_t)blockIdx.x * NKC * CH_B;

    float4 acc[2][8];
#pragma unroll
    for (int mi = 0; mi < 2; ++mi)
#pragma unroll
        for (int ni = 0; ni < 8; ++ni)
            acc[mi][ni] = make_float4(0.f, 0.f, 0.f, 0.f);

    auto issue = [&](int kc, int s) {
        uint32_t dst = dynB + s * STAGE_B;
        const char* ah = gAh + aBase + (size_t)kc * CH_A;
        const char* al = gAl + aBase + (size_t)kc * CH_A;
        const char* bi = gBi + bBase + (size_t)kc * CH_B;
        int off = tid * 16;               // each sweep covers 4KB
        cp16(dst + off, ah + off);
        cp16(dst + 4096 + off, ah + 4096 + off);
        cp16(dst + 8192 + off, al + off);
        cp16(dst + 12288 + off, al + 4096 + off);
        cp16(dst + 16384 + off, bi + off);
        cp16(dst + 20480 + off, bi + 4096 + off);
    };

    issue(0, 0);
    cp_commit();
    issue(1, 1);
    cp_commit();

    for (int kc = 0; kc < NKC; ++kc) {
        const int s = kc % NSTAGE;
        cp_wait1();
        __syncthreads();
        if (kc + 2 < NKC) issue(kc + 2, (kc + 2) % NSTAGE);
        cp_commit();

        const char* st = smem + s * STAGE_B;
#pragma unroll
        for (int kf = 0; kf < 2; ++kf) {
            const char* af = st + (kf * 8 + wm * 2) * 512 + lane * 16;
            uint4 ah0 = *(const uint4*)af;
            uint4 ah1 = *(const uint4*)(af + 512);
            uint4 al0 = *(const uint4*)(af + 8192);
            uint4 al1 = *(const uint4*)(af + 8192 + 512);
            const char* bf =
                st + 16384 + (kf * 8 + wn * 4) * 512 + lane * 16;
#pragma unroll
            for (int p = 0; p < 4; ++p) {
                uint4 b = *(const uint4*)(bf + p * 512);
                int n0 = 2 * p, n1 = 2 * p + 1;
                mma_f16(acc[0][n0], ah0, b.x, b.y);
                mma_f16(acc[1][n0], ah1, b.x, b.y);
                mma_f16(acc[0][n0], al0, b.x, b.y);
                mma_f16(acc[1][n0], al1, b.x, b.y);
                mma_f16(acc[0][n1], ah0, b.z, b.w);
                mma_f16(acc[1][n1], ah1, b.z, b.w);
                mma_f16(acc[0][n1], al0, b.z, b.w);
                mma_f16(acc[1][n1], al1, b.z, b.w);
            }
        }
    }

    const int row0 = blockIdx.y * 128 + wm * 32 + (lane >> 2);
    const int col0 = blockIdx.x * 128 + wn * 64 + (lane & 3) * 2;
#pragma unroll
    for (int ni = 0; ni < 8; ++ni) {
        // acc index ni maps to fragment nf: pairs (2p, 2p+1) are frags
        // wn*8 + 2p and wn*8 + 2p + 1 -> columns wn*64 + ni*8 as before
        int c = col0 + ni * 8;
        float bx = bias[c], by = bias[c + 1];
#pragma unroll
        for (int mi = 0; mi < 2; ++mi) {
            float4 v = acc[mi][ni];
            float* p0 = C + (size_t)(row0 + mi * 16) * N + c;
            float* p1 = C + (size_t)(row0 + mi * 16 + 8) * N + c;
            *(float2*)p0 = make_float2(v.x + bx, v.y + by);
            *(float2*)p1 = make_float2(v.z + bx, v.w + by);
        }
    }
}

// ---------------------------------------------------------------------------
// Windowed attention (lightweight, one block per window).
// Emits output directly as hi/lo fp16 A-fragment images for GEMM2.
// ---------------------------------------------------------------------------
__global__ void __launch_bounds__(256)
win_attn_kernel(const float* __restrict__ qkv, char* __restrict__ oh,
                char* __restrict__ ol) {
    const int win = blockIdx.x;
    const int h = threadIdx.x >> 5;
    const int lane = threadIdx.x & 31;
    const int m0 = win * WIN;

    const float* base = qkv + (size_t)m0 * N_QKV + h * 64;

    float q[WIN][2], k[WIN][2], v[WIN][2];
#pragma unroll
    for (int i = 0; i < WIN; ++i) {
        const float* r = base + (size_t)i * N_QKV;
        q[i][0] = r[lane];        q[i][1] = r[lane + 32];
        k[i][0] = r[512 + lane];  k[i][1] = r[512 + lane + 32];
        v[i][0] = r[1024 + lane]; v[i][1] = r[1024 + lane + 32];
    }

    float s[WIN][WIN];
#pragma unroll
    for (int i = 0; i < WIN; ++i)
#pragma unroll
        for (int j = 0; j < WIN; ++j) {
            float p = q[i][0] * k[j][0] + q[i][1] * k[j][1];
            p += __shfl_xor_sync(0xffffffffu, p, 16);
            p += __shfl_xor_sync(0xffffffffu, p, 8);
            p += __shfl_xor_sync(0xffffffffu, p, 4);
            p += __shfl_xor_sync(0xffffffffu, p, 2);
            p += __shfl_xor_sync(0xffffffffu, p, 1);
            s[i][j] = p * HSCALE;
        }

    const int kf = lane >> 4, c = lane & 15;
    const int inner = ((c & 7) >> 1) * 16 + ((c >> 3) << 1) * 4 + (c & 1) * 2;

#pragma unroll
    for (int i = 0; i < WIN; ++i) {
        float mx = s[i][0];
#pragma unroll
        for (int j = 1; j < WIN; ++j) mx = fmaxf(mx, s[i][j]);
        float sum = 0.0f;
#pragma unroll
        for (int j = 0; j < WIN; ++j) {
            s[i][j] = __expf(s[i][j] - mx);
            sum += s[i][j];
        }
        float inv = 1.0f / sum;
        float o0 = 0.0f, o1 = 0.0f;
#pragma unroll
        for (int j = 0; j < WIN; ++j) {
            float a = s[i][j] * inv;
            o0 += a * v[j][0];
            o1 += a * v[j][1];
        }
        int m = m0 + i;
        int r = m & 15, mf = (m & 127) >> 4;
        size_t tb = ((size_t)(m >> 7) * NKC + 2 * h) * CH_A +
                    (size_t)(kf * 8 + mf) * 512 +
                    (size_t)((r & 7) * 4) * 16 + (size_t)(r >> 3) * 4 + inner;
        unsigned short hs, ls;
        split1(o0, hs, ls);
        *(unsigned short*)(oh + tb) = hs;
        *(unsigned short*)(ol + tb) = ls;
        split1(o1, hs, ls);
        *(unsigned short*)(oh + tb + CH_A) = hs;
        *(unsigned short*)(ol + tb + CH_A) = ls;
    }
}

// ---------------------------------------------------------------------------
// kernel_launch
// ---------------------------------------------------------------------------
extern "C" void kernel_launch(void* const* d_in, const int* in_sizes, int n_in,
                              void* d_out, int out_size) {
    const float* x      = (const float*)d_in[0];
    const float* qkv_w  = (const float*)d_in[1];
    const float* qkv_b  = (const float*)d_in[2];
    const float* proj_w = (const float*)d_in[3];
    const float* proj_b = (const float*)d_in[4];
    float* out = (float*)d_out;

    float* qkvp;
    char *Ah, *Al, *Oh, *Ol, *B1, *B2;
    cudaGetSymbolAddress((void**)&qkvp, g_qkv);
    cudaGetSymbolAddress((void**)&Ah, gA_hi);
    cudaGetSymbolAddress((void**)&Al, gA_lo);
    cudaGetSymbolAddress((void**)&Oh, gO_hi);
    cudaGetSymbolAddress((void**)&Ol, gO_lo);
    cudaGetSymbolAddress((void**)&B1, gB1_i);
    cudaGetSymbolAddress((void**)&B2, gB2_i);

    static bool attr_set = false;
    if (!attr_set) {
        cudaFuncSetAttribute(gemm_hmma_split,
                             cudaFuncAttributeMaxDynamicSharedMemorySize,
                             NSTAGE * STAGE_B);
        attr_set = true;
    }

    conv_A_staged<<<(M_TOK / 128) * NKC, 256>>>(x, Ah, Al);
    conv_W_staged<<<(N_QKV / 128) * NKC, 256>>>(qkv_w, B1, N_QKV);
    conv_W_staged<<<(N_PROJ / 128) * NKC, 256>>>(proj_w, B2, N_PROJ);

    {   // GEMM1 -> g_qkv
        dim3 grid(N_QKV / 128, M_TOK / 128);
        gemm_hmma_split<<<grid, 256, NSTAGE * STAGE_B>>>(Ah, Al, B1,
                                                         qkv_b, qkvp, N_QKV);
    }

    win_attn_kernel<<<M_TOK / WIN, 256>>>(qkvp, Oh, Ol);

    {   // GEMM2 -> out
        dim3 grid(N_PROJ / 128, M_TOK / 128);
        gemm_hmma_split<<<grid, 256, NSTAGE * STAGE_B>>>(Oh, Ol, B2,
                                                         proj_b, out, N_PROJ);
    }
}

// round 7
// speedup vs baseline: 2.5590x; 1.6591x over previous
#include <cuda_runtime.h>
#include <cuda_fp16.h>
#include <cstdint>

// ---------------------------------------------------------------------------
// B=512,N=200,C=512,NH=8,WS=5,HD=64.  M=102400 tokens.
// R7: single-fp16 (1-term) HMMA GEMMs; fp16 qkv intermediate.
// mma.sync m16n8k16.f32.f16.f16.f32, fragment-image pre-layout (validated).
// ---------------------------------------------------------------------------
#define M_TOK   102400
#define K_DIM   512
#define N_QKV   1536
#define N_PROJ  512
#define WIN     5
#define HSCALE  0.125f
#define NKC     16        // K chunks of 32
#define CH_A    8192      // 128x32 fp16 A-image chunk bytes
#define CH_B    8192      // 32x128 fp16 B-image chunk bytes (paired frags)
#define STAGE_B 16384     // A(8K)+B(8K)
#define NSTAGE  3

// ---------------- scratch (device globals; no allocation) ------------------
__device__ __half  g_qkv[(size_t)M_TOK * N_QKV];          // fp16 now
__device__ __half  gA_i[(size_t)M_TOK * K_DIM];           // x as A-image
__device__ __half  gO_i[(size_t)M_TOK * K_DIM];           // attn out A-image
__device__ __half  gB1_i[(size_t)K_DIM * N_QKV];
__device__ __half  gB2_i[(size_t)K_DIM * N_PROJ];

// ---------------------------- helpers ---------------------------------------
__device__ __forceinline__ uint32_t smem_u32(const void* p) {
    uint32_t a;
    asm("{ .reg .u64 t; cvta.to.shared.u64 t, %1; cvt.u32.u64 %0, t; }"
        : "=r"(a) : "l"(p));
    return a;
}
__device__ __forceinline__ void cp16(uint32_t d, const void* s) {
    asm volatile("cp.async.cg.shared.global [%0], [%1], 16;"
                 :: "r"(d), "l"(s) : "memory");
}
__device__ __forceinline__ void cp_commit() {
    asm volatile("cp.async.commit_group;" ::: "memory");
}
__device__ __forceinline__ void cp_wait1() {
    asm volatile("cp.async.wait_group 1;" ::: "memory");
}
__device__ __forceinline__ void mma_f16(float4& d, uint4 a, uint32_t b0,
                                        uint32_t b1) {
    asm volatile(
        "mma.sync.aligned.m16n8k16.row.col.f32.f16.f16.f32 "
        "{%0,%1,%2,%3},{%4,%5,%6,%7},{%8,%9},{%0,%1,%2,%3};"
        : "+f"(d.x), "+f"(d.y), "+f"(d.z), "+f"(d.w)
        : "r"(a.x), "r"(a.y), "r"(a.z), "r"(a.w), "r"(b0), "r"(b1));
}
__device__ __forceinline__ unsigned short h_bits(__half h) {
    return *reinterpret_cast<unsigned short*>(&h);
}
__device__ __forceinline__ unsigned short h_single(float f) {
    __half hh = __float2half(f);
    return h_bits(hh);
}

// A-image inner offset (validated R3-R6):
__device__ __forceinline__ int a_inner(int row, int kin) {
    int kf = kin >> 4, mf = row >> 4, r = row & 15, c = kin & 15;
    return (kf * 8 + mf) * 512 + ((r & 7) * 4 + ((c & 7) >> 1)) * 16 +
           ((r >> 3) + ((c >> 3) << 1)) * 4 + (c & 1) * 2;
}
// Paired B-image inner offset (validated R6):
__device__ __forceinline__ int bp_inner(int kr, int n) {
    int kf = kr >> 4, nfp = n >> 4, odd = (n >> 3) & 1;
    int t = (n & 7) * 4 + ((kr & 7) >> 1);
    return (kf * 8 + nfp) * 512 + t * 16 + odd * 8 + ((kr >> 3) & 1) * 4 +
           (kr & 1) * 2;
}

// ---------------------------------------------------------------------------
// conv A: x [M,512] fp32 -> single fp16 A images, smem-staged.
// block = (m-tile 128, k-chunk 32). grid = 800*16.
// ---------------------------------------------------------------------------
__global__ void __launch_bounds__(256)
conv_A_staged(const float* __restrict__ x, char* __restrict__ ai) {
    __shared__ char sh[CH_A];
    const int mt = blockIdx.x >> 4, kc = blockIdx.x & 15;
    const int t = threadIdx.x;
    const float* src = x + (size_t)mt * 128 * K_DIM + kc * 32;
#pragma unroll
    for (int i = 0; i < 4; ++i) {
        int f = t + i * 256;
        int row = f >> 3, c4 = (f & 7) * 4;
        float4 v = *(const float4*)(src + (size_t)row * K_DIM + c4);
        float vv[4] = {v.x, v.y, v.z, v.w};
#pragma unroll
        for (int jj = 0; jj < 4; ++jj)
            *(unsigned short*)(sh + a_inner(row, c4 + jj)) = h_single(vv[jj]);
    }
    __syncthreads();
    size_t ob = ((size_t)mt * NKC + kc) * CH_A;
    const uint4* shv = (const uint4*)sh;
    uint4* gh = (uint4*)(ai + ob);
    gh[t * 2] = shv[t * 2];
    gh[t * 2 + 1] = shv[t * 2 + 1];
}

// ---------------------------------------------------------------------------
// conv W: W [K,N] fp32 -> single fp16 paired B images, staged (validated R6).
// ---------------------------------------------------------------------------
__global__ void __launch_bounds__(256)
conv_W_staged(const float* __restrict__ w, char* __restrict__ bi, int N) {
    __shared__ char sb[CH_B];
    const int nt = blockIdx.x >> 4, kc = blockIdx.x & 15;
    const int t = threadIdx.x;
    const float* src = w + (size_t)(kc * 32) * N + nt * 128;
#pragma unroll
    for (int i = 0; i < 4; ++i) {
        int f = t + i * 256;
        int kr = f >> 5, nc4 = (f & 31) * 4;
        float4 v = *(const float4*)(src + (size_t)kr * N + nc4);
        float vv[4] = {v.x, v.y, v.z, v.w};
#pragma unroll
        for (int jj = 0; jj < 4; ++jj)
            *(unsigned short*)(sb + bp_inner(kr, nc4 + jj)) = h_single(vv[jj]);
    }
    __syncthreads();
    size_t ob = ((size_t)nt * NKC + kc) * CH_B;
    const uint4* sv = (const uint4*)sb;
    uint4* gv = (uint4*)(bi + ob);
    gv[t * 2] = sv[t * 2];
    gv[t * 2 + 1] = sv[t * 2 + 1];
}

// ---------------------------------------------------------------------------
// 1-term fp16 HMMA GEMM. 128x128 CTA tile, 8 warps (4m x 2n), 3 stages.
// HALF_OUT: write __half (g_qkv) vs float (final out).
// ---------------------------------------------------------------------------
template <bool HALF_OUT>
__global__ void __launch_bounds__(256, 2)
gemm_hmma_1t(const char* __restrict__ gAi, const char* __restrict__ gBi,
             const float* __restrict__ bias, void* __restrict__ Cv, int N) {
    extern __shared__ __align__(128) char smem[];
    const int tid = threadIdx.x;
    const int lane = tid & 31, wid = tid >> 5;
    const int wm = wid & 3, wn = wid >> 2;
    const uint32_t dynB = smem_u32(smem);

    const size_t aBase = (size_t)blockIdx.y * NKC * CH_A;
    const size_t bBase = (size_t)blockIdx.x * NKC * CH_B;

    float4 acc[2][8];
#pragma unroll
    for (int mi = 0; mi < 2; ++mi)
#pragma unroll
        for (int ni = 0; ni < 8; ++ni)
            acc[mi][ni] = make_float4(0.f, 0.f, 0.f, 0.f);

    auto issue = [&](int kc, int s) {
        uint32_t dst = dynB + s * STAGE_B;
        const char* ai = gAi + aBase + (size_t)kc * CH_A;
        const char* bi = gBi + bBase + (size_t)kc * CH_B;
        int off = tid * 16;
        cp16(dst + off, ai + off);
        cp16(dst + 4096 + off, ai + 4096 + off);
        cp16(dst + 8192 + off, bi + off);
        cp16(dst + 12288 + off, bi + 4096 + off);
    };

    issue(0, 0);
    cp_commit();
    issue(1, 1);
    cp_commit();

    for (int kc = 0; kc < NKC; ++kc) {
        const int s = kc % NSTAGE;
        cp_wait1();
        __syncthreads();
        if (kc + 2 < NKC) issue(kc + 2, (kc + 2) % NSTAGE);
        cp_commit();

        const char* st = smem + s * STAGE_B;
#pragma unroll
        for (int kf = 0; kf < 2; ++kf) {
            const char* af = st + (kf * 8 + wm * 2) * 512 + lane * 16;
            uint4 a0 = *(const uint4*)af;
            uint4 a1 = *(const uint4*)(af + 512);
            const char* bf =
                st + 8192 + (kf * 8 + wn * 4) * 512 + lane * 16;
#pragma unroll
            for (int p = 0; p < 4; ++p) {
                uint4 b = *(const uint4*)(bf + p * 512);
                int n0 = 2 * p, n1 = 2 * p + 1;
                mma_f16(acc[0][n0], a0, b.x, b.y);
                mma_f16(acc[1][n0], a1, b.x, b.y);
                mma_f16(acc[0][n1], a0, b.z, b.w);
                mma_f16(acc[1][n1], a1, b.z, b.w);
            }
        }
    }

    const int row0 = blockIdx.y * 128 + wm * 32 + (lane >> 2);
    const int col0 = blockIdx.x * 128 + wn * 64 + (lane & 3) * 2;
#pragma unroll
    for (int ni = 0; ni < 8; ++ni) {
        int c = col0 + ni * 8;
        float bx = bias[c], by = bias[c + 1];
#pragma unroll
        for (int mi = 0; mi < 2; ++mi) {
            float4 v = acc[mi][ni];
            if (HALF_OUT) {
                __half* C = (__half*)Cv;
                __half2* p0 =
                    (__half2*)(C + (size_t)(row0 + mi * 16) * N + c);
                __half2* p1 =
                    (__half2*)(C + (size_t)(row0 + mi * 16 + 8) * N + c);
                *p0 = __floats2half2_rn(v.x + bx, v.y + by);
                *p1 = __floats2half2_rn(v.z + bx, v.w + by);
            } else {
                float* C = (float*)Cv;
                float* p0 = C + (size_t)(row0 + mi * 16) * N + c;
                float* p1 = C + (size_t)(row0 + mi * 16 + 8) * N + c;
                *(float2*)p0 = make_float2(v.x + bx, v.y + by);
                *(float2*)p1 = make_float2(v.z + bx, v.w + by);
            }
        }
    }
}

// ---------------------------------------------------------------------------
// Windowed attention: one block per window; qkv fp16 in, fp16 A-image out.
// ---------------------------------------------------------------------------
__global__ void __launch_bounds__(256)
win_attn_kernel(const __half* __restrict__ qkv, char* __restrict__ oi) {
    const int win = blockIdx.x;
    const int h = threadIdx.x >> 5;
    const int lane = threadIdx.x & 31;
    const int m0 = win * WIN;

    const __half* base = qkv + (size_t)m0 * N_QKV + h * 64;

    float q[WIN][2], k[WIN][2], v[WIN][2];
#pragma unroll
    for (int i = 0; i < WIN; ++i) {
        const __half* r = base + (size_t)i * N_QKV;
        q[i][0] = __half2float(r[lane]);
        q[i][1] = __half2float(r[lane + 32]);
        k[i][0] = __half2float(r[512 + lane]);
        k[i][1] = __half2float(r[512 + lane + 32]);
        v[i][0] = __half2float(r[1024 + lane]);
        v[i][1] = __half2float(r[1024 + lane + 32]);
    }

    float s[WIN][WIN];
#pragma unroll
    for (int i = 0; i < WIN; ++i)
#pragma unroll
        for (int j = 0; j < WIN; ++j) {
            float p = q[i][0] * k[j][0] + q[i][1] * k[j][1];
            p += __shfl_xor_sync(0xffffffffu, p, 16);
            p += __shfl_xor_sync(0xffffffffu, p, 8);
            p += __shfl_xor_sync(0xffffffffu, p, 4);
            p += __shfl_xor_sync(0xffffffffu, p, 2);
            p += __shfl_xor_sync(0xffffffffu, p, 1);
            s[i][j] = p * HSCALE;
        }

    const int kf = lane >> 4, c = lane & 15;
    const int inner = ((c & 7) >> 1) * 16 + ((c >> 3) << 1) * 4 + (c & 1) * 2;

#pragma unroll
    for (int i = 0; i < WIN; ++i) {
        float mx = s[i][0];
#pragma unroll
        for (int j = 1; j < WIN; ++j) mx = fmaxf(mx, s[i][j]);
        float sum = 0.0f;
#pragma unroll
        for (int j = 0; j < WIN; ++j) {
            s[i][j] = __expf(s[i][j] - mx);
            sum += s[i][j];
        }
        float inv = 1.0f / sum;
        float o0 = 0.0f, o1 = 0.0f;
#pragma unroll
        for (int j = 0; j < WIN; ++j) {
            float a = s[i][j] * inv;
            o0 += a * v[j][0];
            o1 += a * v[j][1];
        }
        int m = m0 + i;
        int r = m & 15, mf = (m & 127) >> 4;
        size_t tb = ((size_t)(m >> 7) * NKC + 2 * h) * CH_A +
                    (size_t)(kf * 8 + mf) * 512 +
                    (size_t)((r & 7) * 4) * 16 + (size_t)(r >> 3) * 4 + inner;
        *(unsigned short*)(oi + tb) = h_single(o0);
        *(unsigned short*)(oi + tb + CH_A) = h_single(o1);
    }
}

// ---------------------------------------------------------------------------
// kernel_launch
// ---------------------------------------------------------------------------
extern "C" void kernel_launch(void* const* d_in, const int* in_sizes, int n_in,
                              void* d_out, int out_size) {
    const float* x      = (const float*)d_in[0];
    const float* qkv_w  = (const float*)d_in[1];
    const float* qkv_b  = (const float*)d_in[2];
    const float* proj_w = (const float*)d_in[3];
    const float* proj_b = (const float*)d_in[4];
    float* out = (float*)d_out;

    __half* qkvp;
    char *Ai, *Oi, *B1, *B2;
    cudaGetSymbolAddress((void**)&qkvp, g_qkv);
    cudaGetSymbolAddress((void**)&Ai, gA_i);
    cudaGetSymbolAddress((void**)&Oi, gO_i);
    cudaGetSymbolAddress((void**)&B1, gB1_i);
    cudaGetSymbolAddress((void**)&B2, gB2_i);

    static bool attr_set = false;
    if (!attr_set) {
        cudaFuncSetAttribute(gemm_hmma_1t<true>,
                             cudaFuncAttributeMaxDynamicSharedMemorySize,
                             NSTAGE * STAGE_B);
        cudaFuncSetAttribute(gemm_hmma_1t<false>,
                             cudaFuncAttributeMaxDynamicSharedMemorySize,
                             NSTAGE * STAGE_B);
        attr_set = true;
    }

    conv_A_staged<<<(M_TOK / 128) * NKC, 256>>>(x, Ai);
    conv_W_staged<<<(N_QKV / 128) * NKC, 256>>>(qkv_w, B1, N_QKV);
    conv_W_staged<<<(N_PROJ / 128) * NKC, 256>>>(proj_w, B2, N_PROJ);

    {   // GEMM1 -> g_qkv (fp16)
        dim3 grid(N_QKV / 128, M_TOK / 128);
        gemm_hmma_1t<true><<<grid, 256, NSTAGE * STAGE_B>>>(Ai, B1, qkv_b,
                                                            qkvp, N_QKV);
    }

    win_attn_kernel<<<M_TOK / WIN, 256>>>(qkvp, Oi);

    {   // GEMM2 -> out (fp32)
        dim3 grid(N_PROJ / 128, M_TOK / 128);
        gemm_hmma_1t<false><<<grid, 256, NSTAGE * STAGE_B>>>(Oi, B2, proj_b,
                                                             out, N_PROJ);
    }
}